// round 14
// baseline (speedup 1.0000x reference)
#include <cuda_runtime.h>
#include <cstdint>

#define NB     32
#define NS     577
#define NHID   768
#define NHEADS 12
#define NHD    64
#define M_TOTAL   (NB * NS)                   // 18464
#define QKV_ELEMS (NB * NHEADS * NS * NHD)    // 14,180,352

// q, k, v in [B, NH, S, HD] layout, tf32 bit patterns (Q pre-scaled by 0.125*log2e)
__device__ float g_qkv[3ull * QKV_ELEMS];
// pre-converted tf32 operands for the projection GEMM
__device__ uint32_t g_xt[(size_t)M_TOTAL * NHID];
__device__ uint32_t g_wt[3ull * NHID * NHID];

__device__ __forceinline__ uint32_t f2tf(float f) {
    uint32_t u;
    asm("cvt.rna.tf32.f32 %0, %1;" : "=r"(u) : "f"(f));
    return u;
}

__device__ __forceinline__ float ex2f(float x) {
    float y;
    asm("ex2.approx.f32 %0, %1;" : "=f"(y) : "f"(x));
    return y;
}

__device__ __forceinline__ void mma_tf32(float* d, const uint32_t* a,
                                         uint32_t b0, uint32_t b1) {
    asm volatile(
        "mma.sync.aligned.m16n8k8.row.col.f32.tf32.tf32.f32 "
        "{%0,%1,%2,%3},{%4,%5,%6,%7},{%8,%9},{%0,%1,%2,%3};"
        : "+f"(d[0]), "+f"(d[1]), "+f"(d[2]), "+f"(d[3])
        : "r"(a[0]), "r"(a[1]), "r"(a[2]), "r"(a[3]), "r"(b0), "r"(b1));
}

__device__ __forceinline__ void cpa16(uint32_t dst, const void* src, unsigned nbytes) {
    asm volatile("cp.async.cg.shared.global [%0], [%1], 16, %2;"
                 :: "r"(dst), "l"(src), "r"(nbytes));
}
#define CP_COMMIT() asm volatile("cp.async.commit_group;")
#define CP_WAIT0()  asm volatile("cp.async.wait_group 0;")

// ---------------------------------------------------------------------------
// Kernel 0: convert X and Wq/Wk/Wv to tf32 bit patterns (one pass).
// ---------------------------------------------------------------------------
#define XV  ((size_t)M_TOTAL * NHID / 4)
#define WV  ((size_t)NHID * NHID / 4)
#define CVT_TOTAL (XV + 3 * WV)

__global__ __launch_bounds__(256) void cvt_kernel(
    const float4* __restrict__ X,
    const float4* __restrict__ Wq,
    const float4* __restrict__ Wk,
    const float4* __restrict__ Wv)
{
    size_t i = (size_t)blockIdx.x * 256 + threadIdx.x;
    if (i >= CVT_TOTAL) return;
    const float4* src;
    uint4* dst;
    if (i < XV) {
        src = X + i;
        dst = (uint4*)g_xt + i;
    } else {
        size_t j = i - XV;
        int w = (int)(j / WV);
        size_t r = j % WV;
        src = (w == 0 ? Wq : w == 1 ? Wk : Wv) + r;
        dst = (uint4*)g_wt + (size_t)w * WV + r;
    }
    float4 v = *src;
    uint4 o;
    o.x = f2tf(v.x); o.y = f2tf(v.y); o.z = f2tf(v.z); o.w = f2tf(v.w);
    *dst = o;
}

// ---------------------------------------------------------------------------
// Kernel 1: fused QKV projection, tf32 MMA, cp.async double-buffered, BK=32.
// (unchanged)
// ---------------------------------------------------------------------------
#define BM   128
#define BN   128
#define BK   32
#define STA  36
#define QKV_TILE   (BM * STA)
#define QKV_SMEM_U32 (4 * QKV_TILE)
#define QKV_SMEM_BYTES (QKV_SMEM_U32 * 4)

__global__ __launch_bounds__(256, 2) void qkv_proj_kernel(
    const float* __restrict__ bq,
    const float* __restrict__ bk,
    const float* __restrict__ bv,
    const float* __restrict__ lateral,
    const int*   __restrict__ mixp)
{
    extern __shared__ uint32_t smq[];
    uint32_t* Asm = smq;
    uint32_t* Bsm = smq + 2 * QKV_TILE;

    const int z = blockIdx.z;
    const float* bias = (z == 0) ? bq : (z == 1) ? bk : bv;
    const int mix = __ldg(mixp);
    const float oscale = (z == 0) ? 0.125f * 1.44269504f : 1.0f;

    const uint32_t* Xg = g_xt;
    const uint32_t* Wg = g_wt + (size_t)z * NHID * NHID;

    const int tid  = threadIdx.x;
    const int lane = tid & 31;
    const int warp = tid >> 5;
    const int g    = lane >> 2;
    const int t    = lane & 3;
    const int wm   = (warp >> 2) * 64;
    const int wn   = (warp & 3) * 32;
    const int bm   = blockIdx.x * BM;
    const int bn   = blockIdx.y * BN;

    const uint32_t smem_a = (uint32_t)__cvta_generic_to_shared(Asm);
    const uint32_t smem_b = (uint32_t)__cvta_generic_to_shared(Bsm);

    float acc[4][4][4];
    #pragma unroll
    for (int i = 0; i < 4; i++)
        #pragma unroll
        for (int j = 0; j < 4; j++)
            #pragma unroll
            for (int c = 0; c < 4; c++) acc[i][j][c] = 0.f;

    {
        #pragma unroll
        for (int it = 0; it < 4; it++) {
            int c   = tid + it * 256;
            int row = c >> 3;
            int c4  = (c & 7) * 4;
            int gm  = bm + row;
            unsigned nba = (gm < M_TOTAL) ? 16u : 0u;
            cpa16(smem_a + (row * STA + c4) * 4, Xg + (size_t)gm * NHID + c4, nba);
            cpa16(smem_b + (row * STA + c4) * 4, Wg + (size_t)(bn + row) * NHID + c4, 16u);
        }
        CP_COMMIT();
    }

    const int NKT = NHID / BK;  // 24
    for (int kt = 0; kt < NKT; kt++) {
        const int buf = kt & 1;
        CP_WAIT0();
        __syncthreads();

        if (kt + 1 < NKT) {
            const int nb = buf ^ 1;
            const int kk = (kt + 1) * BK;
            #pragma unroll
            for (int it = 0; it < 4; it++) {
                int c   = tid + it * 256;
                int row = c >> 3;
                int c4  = (c & 7) * 4;
                int gm  = bm + row;
                unsigned nba = (gm < M_TOTAL) ? 16u : 0u;
                cpa16(smem_a + (nb * QKV_TILE + row * STA + c4) * 4,
                      Xg + (size_t)gm * NHID + kk + c4, nba);
                cpa16(smem_b + (nb * QKV_TILE + row * STA + c4) * 4,
                      Wg + (size_t)(bn + row) * NHID + kk + c4, 16u);
            }
            CP_COMMIT();
        }

        const uint32_t* Ab = Asm + buf * QKV_TILE;
        const uint32_t* Bb = Bsm + buf * QKV_TILE;
        #pragma unroll
        for (int ks = 0; ks < BK; ks += 8) {
            uint32_t a[4][4], b[4][2];
            #pragma unroll
            for (int i = 0; i < 4; i++) {
                int m = wm + i * 16 + g;
                a[i][0] = Ab[m * STA + ks + t];
                a[i][1] = Ab[(m + 8) * STA + ks + t];
                a[i][2] = Ab[m * STA + ks + t + 4];
                a[i][3] = Ab[(m + 8) * STA + ks + t + 4];
            }
            #pragma unroll
            for (int j = 0; j < 4; j++) {
                int n = wn + j * 8 + g;
                b[j][0] = Bb[n * STA + ks + t];
                b[j][1] = Bb[n * STA + ks + t + 4];
            }
            #pragma unroll
            for (int i = 0; i < 4; i++)
                #pragma unroll
                for (int j = 0; j < 4; j++)
                    mma_tf32(acc[i][j], a[i], b[j][0], b[j][1]);
        }
    }

    float* dst = g_qkv + (size_t)z * QKV_ELEMS;
    #pragma unroll
    for (int i = 0; i < 4; i++) {
        int gm0 = bm + wm + i * 16 + g;
        int gm1 = gm0 + 8;
        int bb0 = gm0 / NS, ss0 = gm0 % NS;
        int bb1 = gm1 / NS, ss1 = gm1 % NS;
        #pragma unroll
        for (int j = 0; j < 4; j++) {
            int nl = bn + wn + j * 8 + 2 * t;
            int h  = nl >> 6;
            int d  = nl & 63;
            float b0 = bias[nl], b1 = bias[nl + 1];
            if (gm0 < M_TOTAL) {
                size_t i0 = (((size_t)bb0 * NHEADS + h) * NS + ss0) * NHD + d;
                float v0 = acc[i][j][0] + b0;
                float v1 = acc[i][j][1] + b1;
                if (z == mix) { v0 *= lateral[i0]; v1 *= lateral[i0 + 1]; }
                dst[i0]     = __uint_as_float(f2tf(v0 * oscale));
                dst[i0 + 1] = __uint_as_float(f2tf(v1 * oscale));
            }
            if (gm1 < M_TOTAL) {
                size_t i1 = (((size_t)bb1 * NHEADS + h) * NS + ss1) * NHD + d;
                float v2 = acc[i][j][2] + b0;
                float v3 = acc[i][j][3] + b1;
                if (z == mix) { v2 *= lateral[i1]; v3 *= lateral[i1 + 1]; }
                dst[i1]     = __uint_as_float(f2tf(v2 * oscale));
                dst[i1 + 1] = __uint_as_float(f2tf(v3 * oscale));
            }
        }
    }
}

// ---------------------------------------------------------------------------
// Kernel 2: flash attention, REGISTER-RESIDENT P. Warp (mi,ni) computes S for
// rows mi*16 x keys ni*16 of each chunk, exponentiates in-register, shuffle-
// transposes the accumulator into PV A-fragments, and accumulates a partial
// O (16 rows x 64 dims) over its keys. ONE barrier per chunk. Partials merged
// through smem scratch at the end.
// ---------------------------------------------------------------------------
#define BQ2  64
#define QT2  10
#define NCH  10
#define KST  68   // K/Q stride (68 % 32 == 4)
#define VST  72   // V stride   (72 % 32 == 8)

#define OF_K   0
#define OF_V   (2 * 64 * KST)                 // 8704
#define OF_Q   (OF_V + 2 * 64 * VST)          // 17920
#define OF_L   (OF_Q + 64 * KST)              // 22272
#define SMEM_FLOATS (OF_L + 64)               // 22336
#define SMEM_BYTES  (SMEM_FLOATS * 4)         // 89344
#define SCST   68                              // scratch row stride (floats)

__global__ __launch_bounds__(512, 1) void attn_kernel(float* __restrict__ out)
{
    extern __shared__ float smem[];
    uint32_t* Qs    = (uint32_t*)smem + OF_Q;
    float*    row_l = smem + OF_L;
    float*    scratch = smem;    // reused after the chunk loop (17408 < OF_Q)
    const uint32_t smem_u32 = (uint32_t)__cvta_generic_to_shared(smem);

    const int tid  = threadIdx.x;
    const int lane = tid & 31;
    const int warp = tid >> 5;     // 0..15
    const int g    = lane >> 2;
    const int t    = lane & 3;
    const int mi   = warp >> 2;    // query band (16 rows)
    const int ni   = warp & 3;     // key band (16 keys per chunk)

    const int bh = blockIdx.x / QT2;
    const int qt = blockIdx.x % QT2;
    const int q0 = qt * BQ2;
    const int bb = bh / NHEADS;
    const int hh = bh % NHEADS;

    const uint32_t* qptr = (const uint32_t*)g_qkv + (size_t)bh * NS * NHD;
    const uint32_t* kptr = (const uint32_t*)g_qkv + (size_t)QKV_ELEMS + (size_t)bh * NS * NHD;
    const uint32_t* vptr = (const uint32_t*)g_qkv + (size_t)2 * QKV_ELEMS + (size_t)bh * NS * NHD;

    const int row0 = tid >> 4;           // 0..31
    const int c4   = (tid & 15) * 4;     // 0..60

    // issue chunk 0 K/V loads
    #pragma unroll
    for (int it = 0; it < 2; it++) {
        int row = row0 + it * 32;
        cpa16(smem_u32 + (OF_K + row * KST + c4) * 4, kptr + (size_t)row * NHD + c4, 16u);
        cpa16(smem_u32 + (OF_V + row * VST + c4) * 4, vptr + (size_t)row * NHD + c4, 16u);
    }
    CP_COMMIT();

    // load Q tile (raw tf32 bits) into its own region
    #pragma unroll
    for (int it = 0; it < 2; it++) {
        int row = row0 + it * 32;
        int s   = q0 + row;
        uint4 v = (s < NS) ? *(const uint4*)(qptr + (size_t)s * NHD + c4)
                           : make_uint4(0u, 0u, 0u, 0u);
        *(uint4*)(Qs + row * KST + c4) = v;
    }
    if (tid < 64) row_l[tid] = 0.f;
    __syncthreads();

    // hoist Q fragments (16 rows of band mi, 8 k-steps)
    uint32_t aq[8][4];
    {
        int r0 = (mi * 16 + g) * KST;
        int r1 = r0 + 8 * KST;
        #pragma unroll
        for (int ks = 0; ks < 8; ks++) {
            aq[ks][0] = Qs[r0 + ks * 8 + t];
            aq[ks][1] = Qs[r1 + ks * 8 + t];
            aq[ks][2] = Qs[r0 + ks * 8 + t + 4];
            aq[ks][3] = Qs[r1 + ks * 8 + t + 4];
        }
    }

    float lp0 = 0.f, lp1 = 0.f;         // row-sum partials (rows mi*16+g, +8+g)

    // partial O over this warp's keys: 16 rows x 64 dims -> 8 n-tiles x 4 regs
    float accO[8][4];
    #pragma unroll
    for (int jn = 0; jn < 8; jn++)
        #pragma unroll
        for (int c = 0; c < 4; c++) accO[jn][c] = 0.f;

    const int src0 = (lane & 28) | (t >> 1);   // quad-lane shuffle sources
    const int src2 = src0 + 2;

    for (int kt = 0; kt < NCH; kt++) {
        const int buf = kt & 1;
        const uint32_t* kb = (uint32_t*)smem + OF_K + buf * 64 * KST;
        const uint32_t* vb = (uint32_t*)smem + OF_V + buf * 64 * VST;

        CP_WAIT0();
        __syncthreads();   // THE one barrier: buffers ready + prev reads done

        if (kt + 1 < NCH) {
            const int kofs = OF_K + (buf ^ 1) * 64 * KST;
            const int vofs = OF_V + (buf ^ 1) * 64 * VST;
            #pragma unroll
            for (int it = 0; it < 2; it++) {
                int row = row0 + it * 32;
                int gk  = (kt + 1) * 64 + row;
                unsigned nb = (gk < NS) ? 16u : 0u;
                cpa16(smem_u32 + (kofs + row * KST + c4) * 4, kptr + (size_t)gk * NHD + c4, nb);
                cpa16(smem_u32 + (vofs + row * VST + c4) * 4, vptr + (size_t)gk * NHD + c4, nb);
            }
            CP_COMMIT();
        }

        // last chunk: only key 576 (warp ni==0) contributes
        const bool active = (kt < NCH - 1) || (ni == 0);
        if (active) {
            // ---- S = Q @ K_chunk^T for this warp's 16 keys ----
            float sacc[2][4];
            #pragma unroll
            for (int j = 0; j < 2; j++)
                #pragma unroll
                for (int c = 0; c < 4; c++) sacc[j][c] = 0.f;

            #pragma unroll
            for (int ks = 0; ks < 8; ks++) {
                #pragma unroll
                for (int j = 0; j < 2; j++) {
                    int nr = (ni * 16 + j * 8 + g) * KST + ks * 8;
                    mma_tf32(sacc[j], aq[ks], kb[nr + t], kb[nr + t + 4]);
                }
            }

            // ---- exp2 in-register + row sums + shuffle to PV A-fragments ----
            uint32_t pa[2][4];
            #pragma unroll
            for (int j = 0; j < 2; j++) {
                int cl = ni * 16 + j * 8 + 2 * t;
                int gk = kt * 64 + cl;
                bool v0 = gk < NS, v1 = gk + 1 < NS;
                float e00 = v0 ? ex2f(sacc[j][0]) : 0.f;
                float e01 = v1 ? ex2f(sacc[j][1]) : 0.f;
                float e10 = v0 ? ex2f(sacc[j][2]) : 0.f;
                float e11 = v1 ? ex2f(sacc[j][3]) : 0.f;
                lp0 += e00 + e01;
                lp1 += e10 + e11;
                uint32_t u00 = f2tf(e00), u01 = f2tf(e01);
                uint32_t u10 = f2tf(e10), u11 = f2tf(e11);
                // a0 = P[g, t], a1 = P[g+8, t], a2 = P[g, t+4], a3 = P[g+8, t+4]
                uint32_t x0 = __shfl_sync(0xffffffffu, u00, src0);
                uint32_t x1 = __shfl_sync(0xffffffffu, u01, src0);
                pa[j][0] = (t & 1) ? x1 : x0;
                uint32_t y0 = __shfl_sync(0xffffffffu, u10, src0);
                uint32_t y1 = __shfl_sync(0xffffffffu, u11, src0);
                pa[j][1] = (t & 1) ? y1 : y0;
                uint32_t x2 = __shfl_sync(0xffffffffu, u00, src2);
                uint32_t x3 = __shfl_sync(0xffffffffu, u01, src2);
                pa[j][2] = (t & 1) ? x3 : x2;
                uint32_t y2 = __shfl_sync(0xffffffffu, u10, src2);
                uint32_t y3 = __shfl_sync(0xffffffffu, u11, src2);
                pa[j][3] = (t & 1) ? y3 : y2;
            }

            // ---- O += P(this warp's 16 keys) @ V_chunk : all 64 dims ----
            const int njs = (kt < NCH - 1) ? 2 : 1;   // last chunk: 8 keys only
            for (int j = 0; j < njs; j++) {
                int kr = ni * 16 + j * 8;
                #pragma unroll
                for (int jn = 0; jn < 8; jn++) {
                    uint32_t b0 = vb[(kr + t) * VST + jn * 8 + g];
                    uint32_t b1 = vb[(kr + t + 4) * VST + jn * 8 + g];
                    mma_tf32(accO[jn], pa[j], b0, b1);
                }
            }
        }
    }

    // ---- merge row sums ----
    lp0 += __shfl_xor_sync(0xffffffffu, lp0, 1);
    lp0 += __shfl_xor_sync(0xffffffffu, lp0, 2);
    lp1 += __shfl_xor_sync(0xffffffffu, lp1, 1);
    lp1 += __shfl_xor_sync(0xffffffffu, lp1, 2);
    if (t == 0) {
        atomicAdd(&row_l[mi * 16 + g],     lp0);
        atomicAdd(&row_l[mi * 16 + 8 + g], lp1);
    }
    __syncthreads();   // loop done: K/V area free; row_l atomics ordered below

    // ---- stage partial O to scratch[ni][64][SCST] ----
    {
        float* sc = scratch + ni * 64 * SCST;
        int r0 = (mi * 16 + g) * SCST;
        int r1 = r0 + 8 * SCST;
        #pragma unroll
        for (int jn = 0; jn < 8; jn++) {
            int c0 = jn * 8 + 2 * t;
            *(float2*)&sc[r0 + c0] = make_float2(accO[jn][0], accO[jn][1]);
            *(float2*)&sc[r1 + c0] = make_float2(accO[jn][2], accO[jn][3]);
        }
    }
    __syncthreads();

    // ---- reduce 4 partials, normalize, coalesced write ----
    {
        int r  = tid >> 3;            // 0..63
        int d8 = (tid & 7) * 8;       // 0..56
        int s  = q0 + r;
        if (s < NS) {
            float4 s0 = *(float4*)&scratch[r * SCST + d8];
            float4 s1 = *(float4*)&scratch[r * SCST + d8 + 4];
            #pragma unroll
            for (int w = 1; w < 4; w++) {
                float4 a0 = *(float4*)&scratch[w * 64 * SCST + r * SCST + d8];
                float4 a1 = *(float4*)&scratch[w * 64 * SCST + r * SCST + d8 + 4];
                s0.x += a0.x; s0.y += a0.y; s0.z += a0.z; s0.w += a0.w;
                s1.x += a1.x; s1.y += a1.y; s1.z += a1.z; s1.w += a1.w;
            }
            float inv = 1.f / row_l[r];
            s0.x *= inv; s0.y *= inv; s0.z *= inv; s0.w *= inv;
            s1.x *= inv; s1.y *= inv; s1.z *= inv; s1.w *= inv;
            size_t base = ((size_t)bb * NS + s) * NHID + hh * NHD + d8;
            *(float4*)&out[base]     = s0;
            *(float4*)&out[base + 4] = s1;
        }
    }
}

// ---------------------------------------------------------------------------
extern "C" void kernel_launch(void* const* d_in, const int* in_sizes, int n_in,
                              void* d_out, int out_size)
{
    const float* hs  = (const float*)d_in[0];
    const float* lat = (const float*)d_in[1];
    const float* Wq  = (const float*)d_in[2];
    const float* bq  = (const float*)d_in[3];
    const float* Wk  = (const float*)d_in[4];
    const float* bk  = (const float*)d_in[5];
    const float* Wv  = (const float*)d_in[6];
    const float* bv  = (const float*)d_in[7];
    const int*   mix = (const int*)d_in[8];
    float* out = (float*)d_out;

    int cvt_blocks = (int)((CVT_TOTAL + 255) / 256);
    cvt_kernel<<<cvt_blocks, 256>>>((const float4*)hs, (const float4*)Wq,
                                    (const float4*)Wk, (const float4*)Wv);

    cudaFuncSetAttribute(qkv_proj_kernel, cudaFuncAttributeMaxDynamicSharedMemorySize,
                         (int)QKV_SMEM_BYTES);
    dim3 g1((M_TOTAL + BM - 1) / BM, NHID / BN, 3);
    qkv_proj_kernel<<<g1, 256, QKV_SMEM_BYTES>>>(bq, bk, bv, lat, mix);

    cudaFuncSetAttribute(attn_kernel, cudaFuncAttributeMaxDynamicSharedMemorySize,
                         (int)SMEM_BYTES);
    attn_kernel<<<NB * NHEADS * QT2, 512, SMEM_BYTES>>>(out);
}

// round 15
// speedup vs baseline: 1.0015x; 1.0015x over previous
#include <cuda_runtime.h>
#include <cstdint>

#define NB     32
#define NS     577
#define NHID   768
#define NHEADS 12
#define NHD    64
#define M_TOTAL   (NB * NS)                   // 18464
#define QKV_ELEMS (NB * NHEADS * NS * NHD)    // 14,180,352

// q, k, v in [B, NH, S, HD] layout, tf32 bit patterns (Q pre-scaled by 0.125*log2e)
__device__ float g_qkv[3ull * QKV_ELEMS];
// pre-converted tf32 operands for the projection GEMM
__device__ uint32_t g_xt[(size_t)M_TOTAL * NHID];
__device__ uint32_t g_wt[3ull * NHID * NHID];

__device__ __forceinline__ uint32_t f2tf(float f) {
    uint32_t u;
    asm("cvt.rna.tf32.f32 %0, %1;" : "=r"(u) : "f"(f));
    return u;
}

__device__ __forceinline__ float ex2f(float x) {
    float y;
    asm("ex2.approx.f32 %0, %1;" : "=f"(y) : "f"(x));
    return y;
}

__device__ __forceinline__ void mma_tf32(float* d, const uint32_t* a,
                                         uint32_t b0, uint32_t b1) {
    asm volatile(
        "mma.sync.aligned.m16n8k8.row.col.f32.tf32.tf32.f32 "
        "{%0,%1,%2,%3},{%4,%5,%6,%7},{%8,%9},{%0,%1,%2,%3};"
        : "+f"(d[0]), "+f"(d[1]), "+f"(d[2]), "+f"(d[3])
        : "r"(a[0]), "r"(a[1]), "r"(a[2]), "r"(a[3]), "r"(b0), "r"(b1));
}

__device__ __forceinline__ void cpa16(uint32_t dst, const void* src, unsigned nbytes) {
    asm volatile("cp.async.cg.shared.global [%0], [%1], 16, %2;"
                 :: "r"(dst), "l"(src), "r"(nbytes));
}
#define CP_COMMIT() asm volatile("cp.async.commit_group;")
#define CP_WAIT0()  asm volatile("cp.async.wait_group 0;")

// ---------------------------------------------------------------------------
// Kernel 0: convert X and Wq/Wk/Wv to tf32 bit patterns (one pass).
// ---------------------------------------------------------------------------
#define XV  ((size_t)M_TOTAL * NHID / 4)
#define WV  ((size_t)NHID * NHID / 4)
#define CVT_TOTAL (XV + 3 * WV)

__global__ __launch_bounds__(256) void cvt_kernel(
    const float4* __restrict__ X,
    const float4* __restrict__ Wq,
    const float4* __restrict__ Wk,
    const float4* __restrict__ Wv)
{
    size_t i = (size_t)blockIdx.x * 256 + threadIdx.x;
    if (i >= CVT_TOTAL) return;
    const float4* src;
    uint4* dst;
    if (i < XV) {
        src = X + i;
        dst = (uint4*)g_xt + i;
    } else {
        size_t j = i - XV;
        int w = (int)(j / WV);
        size_t r = j % WV;
        src = (w == 0 ? Wq : w == 1 ? Wk : Wv) + r;
        dst = (uint4*)g_wt + (size_t)w * WV + r;
    }
    float4 v = *src;
    uint4 o;
    o.x = f2tf(v.x); o.y = f2tf(v.y); o.z = f2tf(v.z); o.w = f2tf(v.w);
    *dst = o;
}

// ---------------------------------------------------------------------------
// Kernel 1: fused QKV projection, tf32 MMA, cp.async double-buffered, BK=32.
// (unchanged)
// ---------------------------------------------------------------------------
#define BM   128
#define BN   128
#define BK   32
#define STA  36
#define QKV_TILE   (BM * STA)
#define QKV_SMEM_U32 (4 * QKV_TILE)
#define QKV_SMEM_BYTES (QKV_SMEM_U32 * 4)

__global__ __launch_bounds__(256, 2) void qkv_proj_kernel(
    const float* __restrict__ bq,
    const float* __restrict__ bk,
    const float* __restrict__ bv,
    const float* __restrict__ lateral,
    const int*   __restrict__ mixp)
{
    extern __shared__ uint32_t smq[];
    uint32_t* Asm = smq;
    uint32_t* Bsm = smq + 2 * QKV_TILE;

    const int z = blockIdx.z;
    const float* bias = (z == 0) ? bq : (z == 1) ? bk : bv;
    const int mix = __ldg(mixp);
    const float oscale = (z == 0) ? 0.125f * 1.44269504f : 1.0f;

    const uint32_t* Xg = g_xt;
    const uint32_t* Wg = g_wt + (size_t)z * NHID * NHID;

    const int tid  = threadIdx.x;
    const int lane = tid & 31;
    const int warp = tid >> 5;
    const int g    = lane >> 2;
    const int t    = lane & 3;
    const int wm   = (warp >> 2) * 64;
    const int wn   = (warp & 3) * 32;
    const int bm   = blockIdx.x * BM;
    const int bn   = blockIdx.y * BN;

    const uint32_t smem_a = (uint32_t)__cvta_generic_to_shared(Asm);
    const uint32_t smem_b = (uint32_t)__cvta_generic_to_shared(Bsm);

    float acc[4][4][4];
    #pragma unroll
    for (int i = 0; i < 4; i++)
        #pragma unroll
        for (int j = 0; j < 4; j++)
            #pragma unroll
            for (int c = 0; c < 4; c++) acc[i][j][c] = 0.f;

    {
        #pragma unroll
        for (int it = 0; it < 4; it++) {
            int c   = tid + it * 256;
            int row = c >> 3;
            int c4  = (c & 7) * 4;
            int gm  = bm + row;
            unsigned nba = (gm < M_TOTAL) ? 16u : 0u;
            cpa16(smem_a + (row * STA + c4) * 4, Xg + (size_t)gm * NHID + c4, nba);
            cpa16(smem_b + (row * STA + c4) * 4, Wg + (size_t)(bn + row) * NHID + c4, 16u);
        }
        CP_COMMIT();
    }

    const int NKT = NHID / BK;  // 24
    for (int kt = 0; kt < NKT; kt++) {
        const int buf = kt & 1;
        CP_WAIT0();
        __syncthreads();

        if (kt + 1 < NKT) {
            const int nb = buf ^ 1;
            const int kk = (kt + 1) * BK;
            #pragma unroll
            for (int it = 0; it < 4; it++) {
                int c   = tid + it * 256;
                int row = c >> 3;
                int c4  = (c & 7) * 4;
                int gm  = bm + row;
                unsigned nba = (gm < M_TOTAL) ? 16u : 0u;
                cpa16(smem_a + (nb * QKV_TILE + row * STA + c4) * 4,
                      Xg + (size_t)gm * NHID + kk + c4, nba);
                cpa16(smem_b + (nb * QKV_TILE + row * STA + c4) * 4,
                      Wg + (size_t)(bn + row) * NHID + kk + c4, 16u);
            }
            CP_COMMIT();
        }

        const uint32_t* Ab = Asm + buf * QKV_TILE;
        const uint32_t* Bb = Bsm + buf * QKV_TILE;
        #pragma unroll
        for (int ks = 0; ks < BK; ks += 8) {
            uint32_t a[4][4], b[4][2];
            #pragma unroll
            for (int i = 0; i < 4; i++) {
                int m = wm + i * 16 + g;
                a[i][0] = Ab[m * STA + ks + t];
                a[i][1] = Ab[(m + 8) * STA + ks + t];
                a[i][2] = Ab[m * STA + ks + t + 4];
                a[i][3] = Ab[(m + 8) * STA + ks + t + 4];
            }
            #pragma unroll
            for (int j = 0; j < 4; j++) {
                int n = wn + j * 8 + g;
                b[j][0] = Bb[n * STA + ks + t];
                b[j][1] = Bb[n * STA + ks + t + 4];
            }
            #pragma unroll
            for (int i = 0; i < 4; i++)
                #pragma unroll
                for (int j = 0; j < 4; j++)
                    mma_tf32(acc[i][j], a[i], b[j][0], b[j][1]);
        }
    }

    float* dst = g_qkv + (size_t)z * QKV_ELEMS;
    #pragma unroll
    for (int i = 0; i < 4; i++) {
        int gm0 = bm + wm + i * 16 + g;
        int gm1 = gm0 + 8;
        int bb0 = gm0 / NS, ss0 = gm0 % NS;
        int bb1 = gm1 / NS, ss1 = gm1 % NS;
        #pragma unroll
        for (int j = 0; j < 4; j++) {
            int nl = bn + wn + j * 8 + 2 * t;
            int h  = nl >> 6;
            int d  = nl & 63;
            float b0 = bias[nl], b1 = bias[nl + 1];
            if (gm0 < M_TOTAL) {
                size_t i0 = (((size_t)bb0 * NHEADS + h) * NS + ss0) * NHD + d;
                float v0 = acc[i][j][0] + b0;
                float v1 = acc[i][j][1] + b1;
                if (z == mix) { v0 *= lateral[i0]; v1 *= lateral[i0 + 1]; }
                dst[i0]     = __uint_as_float(f2tf(v0 * oscale));
                dst[i0 + 1] = __uint_as_float(f2tf(v1 * oscale));
            }
            if (gm1 < M_TOTAL) {
                size_t i1 = (((size_t)bb1 * NHEADS + h) * NS + ss1) * NHD + d;
                float v2 = acc[i][j][2] + b0;
                float v3 = acc[i][j][3] + b1;
                if (z == mix) { v2 *= lateral[i1]; v3 *= lateral[i1 + 1]; }
                dst[i1]     = __uint_as_float(f2tf(v2 * oscale));
                dst[i1 + 1] = __uint_as_float(f2tf(v3 * oscale));
            }
        }
    }
}

// ---------------------------------------------------------------------------
// Kernel 2: flash attention, REGISTER-RESIDENT P. Warp (mi,ni) computes S for
// rows mi*16 x keys ni*16 of each chunk, exponentiates in-register, shuffle-
// transposes the accumulator into PV A-fragments, and accumulates a partial
// O (16 rows x 64 dims) over its keys. ONE barrier per chunk. Partials merged
// through smem scratch at the end.
// ---------------------------------------------------------------------------
#define BQ2  64
#define QT2  10
#define NCH  10
#define KST  68   // K/Q stride (68 % 32 == 4)
#define VST  72   // V stride   (72 % 32 == 8)

#define OF_K   0
#define OF_V   (2 * 64 * KST)                 // 8704
#define OF_Q   (OF_V + 2 * 64 * VST)          // 17920
#define OF_L   (OF_Q + 64 * KST)              // 22272
#define SMEM_FLOATS (OF_L + 64)               // 22336
#define SMEM_BYTES  (SMEM_FLOATS * 4)         // 89344
#define SCST   68                              // scratch row stride (floats)

__global__ __launch_bounds__(512, 1) void attn_kernel(float* __restrict__ out)
{
    extern __shared__ float smem[];
    uint32_t* Qs    = (uint32_t*)smem + OF_Q;
    float*    row_l = smem + OF_L;
    float*    scratch = smem;    // reused after the chunk loop (17408 < OF_Q)
    const uint32_t smem_u32 = (uint32_t)__cvta_generic_to_shared(smem);

    const int tid  = threadIdx.x;
    const int lane = tid & 31;
    const int warp = tid >> 5;     // 0..15
    const int g    = lane >> 2;
    const int t    = lane & 3;
    const int mi   = warp >> 2;    // query band (16 rows)
    const int ni   = warp & 3;     // key band (16 keys per chunk)

    const int bh = blockIdx.x / QT2;
    const int qt = blockIdx.x % QT2;
    const int q0 = qt * BQ2;
    const int bb = bh / NHEADS;
    const int hh = bh % NHEADS;

    const uint32_t* qptr = (const uint32_t*)g_qkv + (size_t)bh * NS * NHD;
    const uint32_t* kptr = (const uint32_t*)g_qkv + (size_t)QKV_ELEMS + (size_t)bh * NS * NHD;
    const uint32_t* vptr = (const uint32_t*)g_qkv + (size_t)2 * QKV_ELEMS + (size_t)bh * NS * NHD;

    const int row0 = tid >> 4;           // 0..31
    const int c4   = (tid & 15) * 4;     // 0..60

    // issue chunk 0 K/V loads
    #pragma unroll
    for (int it = 0; it < 2; it++) {
        int row = row0 + it * 32;
        cpa16(smem_u32 + (OF_K + row * KST + c4) * 4, kptr + (size_t)row * NHD + c4, 16u);
        cpa16(smem_u32 + (OF_V + row * VST + c4) * 4, vptr + (size_t)row * NHD + c4, 16u);
    }
    CP_COMMIT();

    // load Q tile (raw tf32 bits) into its own region
    #pragma unroll
    for (int it = 0; it < 2; it++) {
        int row = row0 + it * 32;
        int s   = q0 + row;
        uint4 v = (s < NS) ? *(const uint4*)(qptr + (size_t)s * NHD + c4)
                           : make_uint4(0u, 0u, 0u, 0u);
        *(uint4*)(Qs + row * KST + c4) = v;
    }
    if (tid < 64) row_l[tid] = 0.f;
    __syncthreads();

    // hoist Q fragments (16 rows of band mi, 8 k-steps)
    uint32_t aq[8][4];
    {
        int r0 = (mi * 16 + g) * KST;
        int r1 = r0 + 8 * KST;
        #pragma unroll
        for (int ks = 0; ks < 8; ks++) {
            aq[ks][0] = Qs[r0 + ks * 8 + t];
            aq[ks][1] = Qs[r1 + ks * 8 + t];
            aq[ks][2] = Qs[r0 + ks * 8 + t + 4];
            aq[ks][3] = Qs[r1 + ks * 8 + t + 4];
        }
    }

    float lp0 = 0.f, lp1 = 0.f;         // row-sum partials (rows mi*16+g, +8+g)

    // partial O over this warp's keys: 16 rows x 64 dims -> 8 n-tiles x 4 regs
    float accO[8][4];
    #pragma unroll
    for (int jn = 0; jn < 8; jn++)
        #pragma unroll
        for (int c = 0; c < 4; c++) accO[jn][c] = 0.f;

    const int src0 = (lane & 28) | (t >> 1);   // quad-lane shuffle sources
    const int src2 = src0 + 2;

    for (int kt = 0; kt < NCH; kt++) {
        const int buf = kt & 1;
        const uint32_t* kb = (uint32_t*)smem + OF_K + buf * 64 * KST;
        const uint32_t* vb = (uint32_t*)smem + OF_V + buf * 64 * VST;

        CP_WAIT0();
        __syncthreads();   // THE one barrier: buffers ready + prev reads done

        if (kt + 1 < NCH) {
            const int kofs = OF_K + (buf ^ 1) * 64 * KST;
            const int vofs = OF_V + (buf ^ 1) * 64 * VST;
            #pragma unroll
            for (int it = 0; it < 2; it++) {
                int row = row0 + it * 32;
                int gk  = (kt + 1) * 64 + row;
                unsigned nb = (gk < NS) ? 16u : 0u;
                cpa16(smem_u32 + (kofs + row * KST + c4) * 4, kptr + (size_t)gk * NHD + c4, nb);
                cpa16(smem_u32 + (vofs + row * VST + c4) * 4, vptr + (size_t)gk * NHD + c4, nb);
            }
            CP_COMMIT();
        }

        // last chunk: only key 576 (warp ni==0) contributes
        const bool active = (kt < NCH - 1) || (ni == 0);
        if (active) {
            // ---- S = Q @ K_chunk^T for this warp's 16 keys ----
            float sacc[2][4];
            #pragma unroll
            for (int j = 0; j < 2; j++)
                #pragma unroll
                for (int c = 0; c < 4; c++) sacc[j][c] = 0.f;

            #pragma unroll
            for (int ks = 0; ks < 8; ks++) {
                #pragma unroll
                for (int j = 0; j < 2; j++) {
                    int nr = (ni * 16 + j * 8 + g) * KST + ks * 8;
                    mma_tf32(sacc[j], aq[ks], kb[nr + t], kb[nr + t + 4]);
                }
            }

            // ---- exp2 in-register + row sums + shuffle to PV A-fragments ----
            uint32_t pa[2][4];
            #pragma unroll
            for (int j = 0; j < 2; j++) {
                int cl = ni * 16 + j * 8 + 2 * t;
                int gk = kt * 64 + cl;
                bool v0 = gk < NS, v1 = gk + 1 < NS;
                float e00 = v0 ? ex2f(sacc[j][0]) : 0.f;
                float e01 = v1 ? ex2f(sacc[j][1]) : 0.f;
                float e10 = v0 ? ex2f(sacc[j][2]) : 0.f;
                float e11 = v1 ? ex2f(sacc[j][3]) : 0.f;
                lp0 += e00 + e01;
                lp1 += e10 + e11;
                uint32_t u00 = f2tf(e00), u01 = f2tf(e01);
                uint32_t u10 = f2tf(e10), u11 = f2tf(e11);
                // a0 = P[g, t], a1 = P[g+8, t], a2 = P[g, t+4], a3 = P[g+8, t+4]
                uint32_t x0 = __shfl_sync(0xffffffffu, u00, src0);
                uint32_t x1 = __shfl_sync(0xffffffffu, u01, src0);
                pa[j][0] = (t & 1) ? x1 : x0;
                uint32_t y0 = __shfl_sync(0xffffffffu, u10, src0);
                uint32_t y1 = __shfl_sync(0xffffffffu, u11, src0);
                pa[j][1] = (t & 1) ? y1 : y0;
                uint32_t x2 = __shfl_sync(0xffffffffu, u00, src2);
                uint32_t x3 = __shfl_sync(0xffffffffu, u01, src2);
                pa[j][2] = (t & 1) ? x3 : x2;
                uint32_t y2 = __shfl_sync(0xffffffffu, u10, src2);
                uint32_t y3 = __shfl_sync(0xffffffffu, u11, src2);
                pa[j][3] = (t & 1) ? y3 : y2;
            }

            // ---- O += P(this warp's 16 keys) @ V_chunk : all 64 dims ----
            const int njs = (kt < NCH - 1) ? 2 : 1;   // last chunk: 8 keys only
            for (int j = 0; j < njs; j++) {
                int kr = ni * 16 + j * 8;
                #pragma unroll
                for (int jn = 0; jn < 8; jn++) {
                    uint32_t b0 = vb[(kr + t) * VST + jn * 8 + g];
                    uint32_t b1 = vb[(kr + t + 4) * VST + jn * 8 + g];
                    mma_tf32(accO[jn], pa[j], b0, b1);
                }
            }
        }
    }

    // ---- merge row sums ----
    lp0 += __shfl_xor_sync(0xffffffffu, lp0, 1);
    lp0 += __shfl_xor_sync(0xffffffffu, lp0, 2);
    lp1 += __shfl_xor_sync(0xffffffffu, lp1, 1);
    lp1 += __shfl_xor_sync(0xffffffffu, lp1, 2);
    if (t == 0) {
        atomicAdd(&row_l[mi * 16 + g],     lp0);
        atomicAdd(&row_l[mi * 16 + 8 + g], lp1);
    }
    __syncthreads();   // loop done: K/V area free; row_l atomics ordered below

    // ---- stage partial O to scratch[ni][64][SCST] ----
    {
        float* sc = scratch + ni * 64 * SCST;
        int r0 = (mi * 16 + g) * SCST;
        int r1 = r0 + 8 * SCST;
        #pragma unroll
        for (int jn = 0; jn < 8; jn++) {
            int c0 = jn * 8 + 2 * t;
            *(float2*)&sc[r0 + c0] = make_float2(accO[jn][0], accO[jn][1]);
            *(float2*)&sc[r1 + c0] = make_float2(accO[jn][2], accO[jn][3]);
        }
    }
    __syncthreads();

    // ---- reduce 4 partials, normalize, coalesced write ----
    {
        int r  = tid >> 3;            // 0..63
        int d8 = (tid & 7) * 8;       // 0..56
        int s  = q0 + r;
        if (s < NS) {
            float4 s0 = *(float4*)&scratch[r * SCST + d8];
            float4 s1 = *(float4*)&scratch[r * SCST + d8 + 4];
            #pragma unroll
            for (int w = 1; w < 4; w++) {
                float4 a0 = *(float4*)&scratch[w * 64 * SCST + r * SCST + d8];
                float4 a1 = *(float4*)&scratch[w * 64 * SCST + r * SCST + d8 + 4];
                s0.x += a0.x; s0.y += a0.y; s0.z += a0.z; s0.w += a0.w;
                s1.x += a1.x; s1.y += a1.y; s1.z += a1.z; s1.w += a1.w;
            }
            float inv = 1.f / row_l[r];
            s0.x *= inv; s0.y *= inv; s0.z *= inv; s0.w *= inv;
            s1.x *= inv; s1.y *= inv; s1.z *= inv; s1.w *= inv;
            size_t base = ((size_t)bb * NS + s) * NHID + hh * NHD + d8;
            *(float4*)&out[base]     = s0;
            *(float4*)&out[base + 4] = s1;
        }
    }
}

// ---------------------------------------------------------------------------
extern "C" void kernel_launch(void* const* d_in, const int* in_sizes, int n_in,
                              void* d_out, int out_size)
{
    const float* hs  = (const float*)d_in[0];
    const float* lat = (const float*)d_in[1];
    const float* Wq  = (const float*)d_in[2];
    const float* bq  = (const float*)d_in[3];
    const float* Wk  = (const float*)d_in[4];
    const float* bk  = (const float*)d_in[5];
    const float* Wv  = (const float*)d_in[6];
    const float* bv  = (const float*)d_in[7];
    const int*   mix = (const int*)d_in[8];
    float* out = (float*)d_out;

    int cvt_blocks = (int)((CVT_TOTAL + 255) / 256);
    cvt_kernel<<<cvt_blocks, 256>>>((const float4*)hs, (const float4*)Wq,
                                    (const float4*)Wk, (const float4*)Wv);

    cudaFuncSetAttribute(qkv_proj_kernel, cudaFuncAttributeMaxDynamicSharedMemorySize,
                         (int)QKV_SMEM_BYTES);
    dim3 g1((M_TOTAL + BM - 1) / BM, NHID / BN, 3);
    qkv_proj_kernel<<<g1, 256, QKV_SMEM_BYTES>>>(bq, bk, bv, lat, mix);

    cudaFuncSetAttribute(attn_kernel, cudaFuncAttributeMaxDynamicSharedMemorySize,
                         (int)SMEM_BYTES);
    attn_kernel<<<NB * NHEADS * QT2, 512, SMEM_BYTES>>>(out);
}